// round 4
// baseline (speedup 1.0000x reference)
#include <cuda_runtime.h>
#include <cstdint>

// CondConv3d collapses: out[b] = s[b] * (conv3d(x[b], Wsum) + bias_sum)
// Round 4: interior-only x tile (w-halos are constant zeros handled in regs),
//          cp.async 16B fills, LDS.128 weight pairs, FFMA2 compute.

#define B_ 8
#define CIN 32
#define COUT 32
#define DD 16
#define HH_ 64
#define WW 64
#define TAPS 27
#define CC 4                        // input-channel chunk
#define TH 4                        // h rows per block
#define NCHUNK (CIN / CC)           // 8
#define XROWS (CC * 3 * (TH + 2))   // 72 rows
#define XPITCH 64                   // interior only (gw 0..63)
#define XS_FLOATS (XROWS * XPITCH)  // 4608
#define WS_FLOATS (CC * TAPS * COUT)// 3456
#define STAGE_FLOATS (XS_FLOATS + WS_FLOATS) // 8064
#define NSLOT (XROWS * 16)          // 1152 float4 slots
#define NXK 5                       // ceil(1152/256)

__device__ float g_wsum[CIN * TAPS * COUT];  // [c][t][o]
__device__ float g_bias[COUT];
__device__ float g_s[B_];

__global__ void prep_kernel(const float* __restrict__ weight,
                            const float* __restrict__ bias,
                            const float* __restrict__ rw) {
    int idx = blockIdx.x * 256 + threadIdx.x;
    if (idx < CIN * TAPS * COUT) {
        int o = idx & 31;
        int t = (idx >> 5) % TAPS;
        int c = idx / (32 * TAPS);
        int base = (o * CIN + c) * TAPS + t;   // weight: [e][o][c][t]
        float s = 0.f;
        #pragma unroll
        for (int e = 0; e < 8; e++) s += weight[e * (COUT * CIN * TAPS) + base];
        g_wsum[(c * TAPS + t) * COUT + o] = s;
    }
    if (blockIdx.x == 0) {
        int tid = threadIdx.x;
        if (tid < COUT) {
            float s = 0.f;
            #pragma unroll
            for (int e = 0; e < 8; e++) s += bias[e * COUT + tid];
            g_bias[tid] = s;
        } else if (tid < COUT + B_) {
            int b = tid - COUT;
            float s = 0.f;
            #pragma unroll
            for (int e = 0; e < 8; e++) s += rw[b * 8 + e];
            g_s[b] = s;
        }
    }
}

// ---- packed f32x2 helpers ----
__device__ __forceinline__ unsigned long long bcast2(float v) {
    unsigned long long r;
    asm("mov.b64 %0, {%1, %1};" : "=l"(r) : "f"(v));
    return r;
}
__device__ __forceinline__ void ffma2(unsigned long long& d,
                                      unsigned long long a,
                                      unsigned long long b) {
    asm("fma.rn.f32x2 %0, %1, %2, %0;" : "+l"(d) : "l"(a), "l"(b));
}
__device__ __forceinline__ void unpack2(unsigned long long v, float& lo, float& hi) {
    asm("mov.b64 {%0, %1}, %2;" : "=f"(lo), "=f"(hi) : "l"(v));
}

// ---- cp.async helpers ----
__device__ __forceinline__ void cp16_zfill(uint32_t saddr, const float* g, int srcsz) {
    asm volatile("cp.async.cg.shared.global [%0], [%1], 16, %2;"
                 :: "r"(saddr), "l"(g), "r"(srcsz));
}
__device__ __forceinline__ void cp16(uint32_t saddr, const float* g) {
    asm volatile("cp.async.cg.shared.global [%0], [%1], 16;"
                 :: "r"(saddr), "l"(g));
}
__device__ __forceinline__ void cp_commit() {
    asm volatile("cp.async.commit_group;");
}
__device__ __forceinline__ void cp_wait1() {
    asm volatile("cp.async.wait_group 1;");
}
__device__ __forceinline__ void cp_wait0() {
    asm volatile("cp.async.wait_group 0;");
}

extern __shared__ float smem_dyn[];

__global__ __launch_bounds__(256, 2) void conv_kernel(const float* __restrict__ x,
                                                      float* __restrict__ out) {
    const int tid = threadIdx.x;
    const int hh = tid >> 6;          // 0..3
    const int og = (tid >> 3) & 7;    // 0..7
    const int wg = tid & 7;           // 0..7
    const int w0 = wg * 8;

    const int h0 = blockIdx.x * TH;
    const int d  = blockIdx.y;
    const int b  = blockIdx.z;

    const float* __restrict__ xb = x + (size_t)b * CIN * DD * HH_ * WW;
    const uint32_t smem_u32 = (uint32_t)__cvta_generic_to_shared(smem_dyn);

    // ---- hoisted x-tile addressing (float4 slots, constant across chunks) ----
    int      goff[NXK];    // float offset into xb for ch=0 (0 when invalid)
    uint32_t soff[NXK];    // byte offset within xs stage
    unsigned mrange = 0, mvalid = 0;
    #pragma unroll
    for (int k = 0; k < NXK; k++) {
        int s = tid + 256 * k;
        int row = s >> 4;            // 0..71
        int q   = s & 15;            // float4 index within row
        int rr  = row % (TH + 2);
        int dz  = (row / (TH + 2)) % 3;
        int cl  = row / (3 * (TH + 2));
        int gh  = h0 - 1 + rr;
        int gd  = d - 1 + dz;
        bool inr = (s < NSLOT);
        bool val = inr && (gh >= 0) && (gh < HH_) && (gd >= 0) && (gd < DD);
        goff[k] = val ? (((cl * DD + gd) * HH_ + gh) * WW + 4 * q) : 0;
        soff[k] = (uint32_t)((row * XPITCH + 4 * q) * 4);
        if (inr) mrange |= 1u << k;
        if (val) mvalid |= 1u << k;
    }

    // ---- prefetch chunk 0 ----
    {
        uint32_t xs_u = smem_u32;
        uint32_t ws_u = smem_u32 + XS_FLOATS * 4;
        #pragma unroll
        for (int k = 0; k < NXK; k++) {
            if ((mrange >> k) & 1)
                cp16_zfill(xs_u + soff[k], xb + goff[k], ((mvalid >> k) & 1) * 16);
        }
        #pragma unroll
        for (int k = 0; k < 4; k++) {
            int idx = tid + k * 256;            // float4 index, total 864
            if (idx < WS_FLOATS / 4)
                cp16(ws_u + idx * 16, g_wsum + idx * 4);
        }
        cp_commit();
    }

    // acc2[op][wi]: lanes = output channels (og*4+2*op, +1)
    unsigned long long acc2[2][8];
    #pragma unroll
    for (int op = 0; op < 2; op++)
        #pragma unroll
        for (int wi = 0; wi < 8; wi++) acc2[op][wi] = 0ull;

    #pragma unroll 1
    for (int ch = 0; ch < NCHUNK; ch++) {
        const int stage = ch & 1;
        if (ch + 1 < NCHUNK) {
            const int ns = (ch + 1) & 1;
            const float* gx = xb + (size_t)(ch + 1) * CC * DD * HH_ * WW;
            uint32_t xs_u = smem_u32 + ns * STAGE_FLOATS * 4;
            uint32_t ws_u = xs_u + XS_FLOATS * 4;
            #pragma unroll
            for (int k = 0; k < NXK; k++) {
                if ((mrange >> k) & 1)
                    cp16_zfill(xs_u + soff[k], gx + goff[k], ((mvalid >> k) & 1) * 16);
            }
            const float* gw4 = g_wsum + (ch + 1) * WS_FLOATS;
            #pragma unroll
            for (int k = 0; k < 4; k++) {
                int idx = tid + k * 256;
                if (idx < WS_FLOATS / 4)
                    cp16(ws_u + idx * 16, gw4 + idx * 4);
            }
            cp_commit();
            cp_wait1();
        } else {
            cp_wait0();
        }
        __syncthreads();

        const float* xsb = smem_dyn + stage * STAGE_FLOATS;
        const float* wsb = xsb + XS_FLOATS;

        #pragma unroll 1
        for (int cl = 0; cl < CC; cl++) {
            #pragma unroll
            for (int kd = 0; kd < 3; kd++) {
                #pragma unroll
                for (int kh = 0; kh < 3; kh++) {
                    const float* row =
                        xsb + ((cl * 3 + kd) * (TH + 2) + hh + kh) * XPITCH;
                    // interior: two aligned float4; halos: predicated scalars
                    float4 m0 = *reinterpret_cast<const float4*>(row + w0);
                    float4 m1 = *reinterpret_cast<const float4*>(row + w0 + 4);
                    float left  = (wg > 0) ? row[w0 - 1] : 0.f;
                    float right = (wg < 7) ? row[w0 + 8] : 0.f;
                    unsigned long long xp[10];
                    xp[0] = bcast2(left);
                    xp[1] = bcast2(m0.x); xp[2] = bcast2(m0.y);
                    xp[3] = bcast2(m0.z); xp[4] = bcast2(m0.w);
                    xp[5] = bcast2(m1.x); xp[6] = bcast2(m1.y);
                    xp[7] = bcast2(m1.z); xp[8] = bcast2(m1.w);
                    xp[9] = bcast2(right);
                    #pragma unroll
                    for (int kw = 0; kw < 3; kw++) {
                        const int t = kd * 9 + kh * 3 + kw;
                        // one LDS.128 fetches both o-pairs for this tap
                        const ulonglong2 wp =
                            *reinterpret_cast<const ulonglong2*>(
                                wsb + (cl * TAPS + t) * COUT + og * 4);
                        #pragma unroll
                        for (int wi = 0; wi < 8; wi++)
                            ffma2(acc2[0][wi], wp.x, xp[wi + kw]);
                        #pragma unroll
                        for (int wi = 0; wi < 8; wi++)
                            ffma2(acc2[1][wi], wp.y, xp[wi + kw]);
                    }
                }
            }
        }
        __syncthreads();
    }

    // ---- epilogue ----
    const float sb = g_s[b];
    const int h = h0 + hh;
    float accs[4][8];
    #pragma unroll
    for (int op = 0; op < 2; op++)
        #pragma unroll
        for (int wi = 0; wi < 8; wi++)
            unpack2(acc2[op][wi], accs[op * 2][wi], accs[op * 2 + 1][wi]);

    #pragma unroll
    for (int oi = 0; oi < 4; oi++) {
        const int o = og * 4 + oi;
        const float bs = g_bias[o];
        float4 v0, v1;
        v0.x = sb * (accs[oi][0] + bs);
        v0.y = sb * (accs[oi][1] + bs);
        v0.z = sb * (accs[oi][2] + bs);
        v0.w = sb * (accs[oi][3] + bs);
        v1.x = sb * (accs[oi][4] + bs);
        v1.y = sb * (accs[oi][5] + bs);
        v1.z = sb * (accs[oi][6] + bs);
        v1.w = sb * (accs[oi][7] + bs);
        float* op_ = out + (((size_t)(b * COUT + o) * DD + d) * HH_ + h) * WW + w0;
        *reinterpret_cast<float4*>(op_) = v0;
        *reinterpret_cast<float4*>(op_ + 4) = v1;
    }
}

extern "C" void kernel_launch(void* const* d_in, const int* in_sizes, int n_in,
                              void* d_out, int out_size) {
    // x: 16777216, rw: 64, weight: 221184, bias: 256
    const float *x = nullptr, *rw = nullptr, *wt = nullptr, *bi = nullptr;
    for (int i = 0; i < n_in; i++) {
        if (in_sizes[i] == 16777216)     x  = (const float*)d_in[i];
        else if (in_sizes[i] == 221184)  wt = (const float*)d_in[i];
        else if (in_sizes[i] == 256)     bi = (const float*)d_in[i];
        else if (in_sizes[i] == 64)      rw = (const float*)d_in[i];
    }
    float* out = (float*)d_out;

    cudaFuncSetAttribute(conv_kernel,
                         cudaFuncAttributeMaxDynamicSharedMemorySize,
                         2 * STAGE_FLOATS * 4);

    prep_kernel<<<(CIN * TAPS * COUT + 255) / 256, 256>>>(wt, bi, rw);

    dim3 grid(HH_ / TH, DD, B_);   // (16, 16, 8)
    conv_kernel<<<grid, 256, 2 * STAGE_FLOATS * 4>>>(x, out);
}

// round 5
// speedup vs baseline: 1.0908x; 1.0908x over previous
#include <cuda_runtime.h>
#include <cstdint>

// CondConv3d collapses: out[b] = s[b] * (conv3d(x[b], Wsum) + bias_sum)
// Round 5: 3 CTAs/SM (regs<=84 via formula smem addressing), interior-only
//          x tile, cp.async 16B fills, FFMA2 compute, LDS.64 weight pairs.

#define B_ 8
#define CIN 32
#define COUT 32
#define DD 16
#define HH_ 64
#define WW 64
#define TAPS 27
#define CC 4                        // input-channel chunk
#define TH 4                        // h rows per block
#define NCHUNK (CIN / CC)           // 8
#define XROWS (CC * 3 * (TH + 2))   // 72 rows
#define XPITCH 64                   // interior only (gw 0..63) -> soff = s*16
#define XS_FLOATS (XROWS * XPITCH)  // 4608
#define WS_FLOATS (CC * TAPS * COUT)// 3456
#define STAGE_FLOATS (XS_FLOATS + WS_FLOATS) // 8064
#define NSLOT (XROWS * 16)          // 1152 float4 slots
#define NXK 5                       // ceil(1152/256)

__device__ float g_wsum[CIN * TAPS * COUT];  // [c][t][o]
__device__ float g_bias[COUT];
__device__ float g_s[B_];

__global__ void prep_kernel(const float* __restrict__ weight,
                            const float* __restrict__ bias,
                            const float* __restrict__ rw) {
    int idx = blockIdx.x * 256 + threadIdx.x;
    if (idx < CIN * TAPS * COUT) {
        int o = idx & 31;
        int t = (idx >> 5) % TAPS;
        int c = idx / (32 * TAPS);
        int base = (o * CIN + c) * TAPS + t;   // weight: [e][o][c][t]
        float s = 0.f;
        #pragma unroll
        for (int e = 0; e < 8; e++) s += weight[e * (COUT * CIN * TAPS) + base];
        g_wsum[(c * TAPS + t) * COUT + o] = s;
    }
    if (blockIdx.x == 0) {
        int tid = threadIdx.x;
        if (tid < COUT) {
            float s = 0.f;
            #pragma unroll
            for (int e = 0; e < 8; e++) s += bias[e * COUT + tid];
            g_bias[tid] = s;
        } else if (tid < COUT + B_) {
            int b = tid - COUT;
            float s = 0.f;
            #pragma unroll
            for (int e = 0; e < 8; e++) s += rw[b * 8 + e];
            g_s[b] = s;
        }
    }
}

// ---- packed f32x2 helpers ----
__device__ __forceinline__ unsigned long long bcast2(float v) {
    unsigned long long r;
    asm("mov.b64 %0, {%1, %1};" : "=l"(r) : "f"(v));
    return r;
}
__device__ __forceinline__ void ffma2(unsigned long long& d,
                                      unsigned long long a,
                                      unsigned long long b) {
    asm("fma.rn.f32x2 %0, %1, %2, %0;" : "+l"(d) : "l"(a), "l"(b));
}
__device__ __forceinline__ void unpack2(unsigned long long v, float& lo, float& hi) {
    asm("mov.b64 {%0, %1}, %2;" : "=f"(lo), "=f"(hi) : "l"(v));
}

// ---- cp.async helpers ----
__device__ __forceinline__ void cp16_zfill(uint32_t saddr, const float* g, int srcsz) {
    asm volatile("cp.async.cg.shared.global [%0], [%1], 16, %2;"
                 :: "r"(saddr), "l"(g), "r"(srcsz));
}
__device__ __forceinline__ void cp16(uint32_t saddr, const float* g) {
    asm volatile("cp.async.cg.shared.global [%0], [%1], 16;"
                 :: "r"(saddr), "l"(g));
}
__device__ __forceinline__ void cp_commit() {
    asm volatile("cp.async.commit_group;");
}
__device__ __forceinline__ void cp_wait1() {
    asm volatile("cp.async.wait_group 1;");
}
__device__ __forceinline__ void cp_wait0() {
    asm volatile("cp.async.wait_group 0;");
}

extern __shared__ float smem_dyn[];

__global__ __launch_bounds__(256, 3) void conv_kernel(const float* __restrict__ x,
                                                      float* __restrict__ out) {
    const int tid = threadIdx.x;
    const int hh = tid >> 6;          // 0..3
    const int og = (tid >> 3) & 7;    // 0..7
    const int wg = tid & 7;           // 0..7
    const int w0 = wg * 8;

    const int h0 = blockIdx.x * TH;
    const int d  = blockIdx.y;
    const int b  = blockIdx.z;

    const float* __restrict__ xb = x + (size_t)b * CIN * DD * HH_ * WW;
    const uint32_t smem_u32 = (uint32_t)__cvta_generic_to_shared(smem_dyn);

    // ---- hoisted x-tile addressing; smem offset is the linear formula s*16 ----
    int goff[NXK];                 // float offset into xb for ch=0 (0 if invalid)
    unsigned mrange = 0, mvalid = 0;
    #pragma unroll
    for (int k = 0; k < NXK; k++) {
        int s = tid + 256 * k;
        int row = s >> 4;            // 0..71
        int q   = s & 15;            // float4 index within row
        int rr  = row % (TH + 2);
        int dz  = (row / (TH + 2)) % 3;
        int cl  = row / (3 * (TH + 2));
        int gh  = h0 - 1 + rr;
        int gd  = d - 1 + dz;
        bool inr = (s < NSLOT);
        bool val = inr && (gh >= 0) && (gh < HH_) && (gd >= 0) && (gd < DD);
        goff[k] = val ? (((cl * DD + gd) * HH_ + gh) * WW + 4 * q) : 0;
        if (inr) mrange |= 1u << k;
        if (val) mvalid |= 1u << k;
    }
    const uint32_t soff0 = smem_u32 + tid * 16;   // + k*4096 per slot

    // ---- prefetch chunk 0 ----
    {
        uint32_t ws_u = smem_u32 + XS_FLOATS * 4;
        #pragma unroll
        for (int k = 0; k < NXK; k++) {
            if ((mrange >> k) & 1)
                cp16_zfill(soff0 + k * 4096, xb + goff[k], ((mvalid >> k) & 1) * 16);
        }
        #pragma unroll
        for (int k = 0; k < 4; k++) {
            int idx = tid + k * 256;            // float4 index, total 864
            if (idx < WS_FLOATS / 4)
                cp16(ws_u + idx * 16, g_wsum + idx * 4);
        }
        cp_commit();
    }

    // acc2[op][wi]: lanes = output channels (og*4+2*op, +1)
    unsigned long long acc2[2][8];
    #pragma unroll
    for (int op = 0; op < 2; op++)
        #pragma unroll
        for (int wi = 0; wi < 8; wi++) acc2[op][wi] = 0ull;

    #pragma unroll 1
    for (int ch = 0; ch < NCHUNK; ch++) {
        const int stage = ch & 1;
        if (ch + 1 < NCHUNK) {
            const int ns = (ch + 1) & 1;
            const float* gx = xb + (size_t)(ch + 1) * CC * DD * HH_ * WW;
            uint32_t st_u = soff0 + ns * STAGE_FLOATS * 4;
            uint32_t ws_u = smem_u32 + (ns * STAGE_FLOATS + XS_FLOATS) * 4;
            #pragma unroll
            for (int k = 0; k < NXK; k++) {
                if ((mrange >> k) & 1)
                    cp16_zfill(st_u + k * 4096, gx + goff[k], ((mvalid >> k) & 1) * 16);
            }
            const float* gw4 = g_wsum + (ch + 1) * WS_FLOATS;
            #pragma unroll
            for (int k = 0; k < 4; k++) {
                int idx = tid + k * 256;
                if (idx < WS_FLOATS / 4)
                    cp16(ws_u + idx * 16, gw4 + idx * 4);
            }
            cp_commit();
            cp_wait1();
        } else {
            cp_wait0();
        }
        __syncthreads();

        const float* xsb = smem_dyn + stage * STAGE_FLOATS;
        const float* wsb = xsb + XS_FLOATS;

        #pragma unroll 1
        for (int cl = 0; cl < CC; cl++) {
            #pragma unroll
            for (int kd = 0; kd < 3; kd++) {
                #pragma unroll
                for (int kh = 0; kh < 3; kh++) {
                    const float* row =
                        xsb + ((cl * 3 + kd) * (TH + 2) + hh + kh) * XPITCH;
                    float4 m0 = *reinterpret_cast<const float4*>(row + w0);
                    float4 m1 = *reinterpret_cast<const float4*>(row + w0 + 4);
                    float left  = (wg > 0) ? row[w0 - 1] : 0.f;
                    float right = (wg < 7) ? row[w0 + 8] : 0.f;
                    unsigned long long xp[10];
                    xp[0] = bcast2(left);
                    xp[1] = bcast2(m0.x); xp[2] = bcast2(m0.y);
                    xp[3] = bcast2(m0.z); xp[4] = bcast2(m0.w);
                    xp[5] = bcast2(m1.x); xp[6] = bcast2(m1.y);
                    xp[7] = bcast2(m1.z); xp[8] = bcast2(m1.w);
                    xp[9] = bcast2(right);
                    #pragma unroll
                    for (int kw = 0; kw < 3; kw++) {
                        const int t = kd * 9 + kh * 3 + kw;
                        const float* wrow = wsb + (cl * TAPS + t) * COUT + og * 4;
                        const unsigned long long wp0 =
                            *reinterpret_cast<const unsigned long long*>(wrow);
                        const unsigned long long wp1 =
                            *reinterpret_cast<const unsigned long long*>(wrow + 2);
                        #pragma unroll
                        for (int wi = 0; wi < 8; wi++)
                            ffma2(acc2[0][wi], wp0, xp[wi + kw]);
                        #pragma unroll
                        for (int wi = 0; wi < 8; wi++)
                            ffma2(acc2[1][wi], wp1, xp[wi + kw]);
                    }
                }
            }
        }
        __syncthreads();
    }

    // ---- epilogue ----
    const float sb = g_s[b];
    const int h = h0 + hh;
    float accs[4][8];
    #pragma unroll
    for (int op = 0; op < 2; op++)
        #pragma unroll
        for (int wi = 0; wi < 8; wi++)
            unpack2(acc2[op][wi], accs[op * 2][wi], accs[op * 2 + 1][wi]);

    #pragma unroll
    for (int oi = 0; oi < 4; oi++) {
        const int o = og * 4 + oi;
        const float bs = g_bias[o];
        float4 v0, v1;
        v0.x = sb * (accs[oi][0] + bs);
        v0.y = sb * (accs[oi][1] + bs);
        v0.z = sb * (accs[oi][2] + bs);
        v0.w = sb * (accs[oi][3] + bs);
        v1.x = sb * (accs[oi][4] + bs);
        v1.y = sb * (accs[oi][5] + bs);
        v1.z = sb * (accs[oi][6] + bs);
        v1.w = sb * (accs[oi][7] + bs);
        float* op_ = out + (((size_t)(b * COUT + o) * DD + d) * HH_ + h) * WW + w0;
        *reinterpret_cast<float4*>(op_) = v0;
        *reinterpret_cast<float4*>(op_ + 4) = v1;
    }
}

extern "C" void kernel_launch(void* const* d_in, const int* in_sizes, int n_in,
                              void* d_out, int out_size) {
    // x: 16777216, rw: 64, weight: 221184, bias: 256
    const float *x = nullptr, *rw = nullptr, *wt = nullptr, *bi = nullptr;
    for (int i = 0; i < n_in; i++) {
        if (in_sizes[i] == 16777216)     x  = (const float*)d_in[i];
        else if (in_sizes[i] == 221184)  wt = (const float*)d_in[i];
        else if (in_sizes[i] == 256)     bi = (const float*)d_in[i];
        else if (in_sizes[i] == 64)      rw = (const float*)d_in[i];
    }
    float* out = (float*)d_out;

    cudaFuncSetAttribute(conv_kernel,
                         cudaFuncAttributeMaxDynamicSharedMemorySize,
                         2 * STAGE_FLOATS * 4);

    prep_kernel<<<(CIN * TAPS * COUT + 255) / 256, 256>>>(wt, bi, rw);

    dim3 grid(HH_ / TH, DD, B_);   // (16, 16, 8)
    conv_kernel<<<grid, 256, 2 * STAGE_FLOATS * 4>>>(x, out);
}

// round 8
// speedup vs baseline: 3.3875x; 3.1056x over previous
#include <cuda_runtime.h>
#include <cstdint>

// CondConv3d via tf32 mma.sync implicit GEMM (tensor pipe; compute_103-safe,
// no tcgen05). Round 8 = Round 7 with the stage_x cp.async granularity bug
// fixed (16-BYTE copies, 4 floats each; rows need 16 chunks, not 4).
//
// out[b] = s[b] * (conv3d(x[b], Wsum) + bias_sum)
// Per block (b, d, 8 h-rows): D[M=512 pos, N=32 o] = sum over 27 taps x 32 c.
// x in smem c-major xT[c][pos] (pos = hh2*68 + ww3), staged directly by
// cp.async; kw/kh shifts are A-row index offsets; kd via dz restage;
// w-halos are baked zero slots (ww3 64/65), h/d-halos are cp.async zfill.

#define B_ 8
#define CIN 32
#define COUT 32
#define DD 16
#define HH_ 64
#define WW 64

#define XT_PITCH 680               // floats per c (10 rows x 68); 680 % 32 == 8
#define ROW_PITCH 68               // floats per row (64 data + 2 zero + 2 pad)
#define XT_FLOATS (CIN * XT_PITCH) // 21760
#define WPC 36                     // W pitch over c (36 % 32 == 4 -> conflict-free)
#define W_TAP (COUT * WPC)         // 1152 floats per tap
#define W_FLOATS (27 * W_TAP)      // 31104
#define OFF_XT 0
#define OFF_W XT_FLOATS
#define SMEM_FLOATS (XT_FLOATS + W_FLOATS)   // 52864 -> 211456 B

__device__ float g_wt[W_FLOATS];   // [tap][o][c36], expert-summed, tf32-rounded
__device__ float g_bias[COUT];
__device__ float g_s[B_];

__device__ __forceinline__ float to_tf32(float v) {
    uint32_t u;
    asm("cvt.rna.tf32.f32 %0, %1;" : "=r"(u) : "f"(v));
    return __uint_as_float(u);
}

__global__ void prep_kernel(const float* __restrict__ weight,
                            const float* __restrict__ bias,
                            const float* __restrict__ rw) {
    int idx = blockIdx.x * 256 + threadIdx.x;
    if (idx < W_FLOATS) {
        int t = idx / W_TAP;
        int rem = idx % W_TAP;
        int o = rem / WPC;
        int c = rem % WPC;
        float v = 0.f;
        if (c < 32) {
            #pragma unroll
            for (int e = 0; e < 8; e++)
                v += weight[((e * 32 + o) * 32 + c) * 27 + t];
            v = to_tf32(v);
        }
        g_wt[idx] = v;
    }
    if (blockIdx.x == 0) {
        int tid = threadIdx.x;
        if (tid < COUT) {
            float s = 0.f;
            #pragma unroll
            for (int e = 0; e < 8; e++) s += bias[e * COUT + tid];
            g_bias[tid] = s;
        } else if (tid < COUT + B_) {
            int b = tid - COUT;
            float s = 0.f;
            #pragma unroll
            for (int e = 0; e < 8; e++) s += rw[b * 8 + e];
            g_s[b] = s;
        }
    }
}

// ---- cp.async helpers (cp-size is BYTES: 16 B = 4 floats) ----
__device__ __forceinline__ void cp16_zfill(uint32_t saddr, const float* g, int srcsz) {
    asm volatile("cp.async.cg.shared.global [%0], [%1], 16, %2;"
                 :: "r"(saddr), "l"(g), "r"(srcsz));
}
__device__ __forceinline__ void cp16(uint32_t saddr, const float* g) {
    asm volatile("cp.async.cg.shared.global [%0], [%1], 16;"
                 :: "r"(saddr), "l"(g));
}
__device__ __forceinline__ void cp_commit() { asm volatile("cp.async.commit_group;"); }
__device__ __forceinline__ void cp_wait0()  { asm volatile("cp.async.wait_group 0;"); }

__device__ __forceinline__ void mma_tf32(float* c, uint32_t a0, uint32_t a1,
                                         uint32_t a2, uint32_t a3,
                                         uint32_t b0, uint32_t b1) {
    asm volatile("mma.sync.aligned.m16n8k8.row.col.f32.tf32.tf32.f32 "
                 "{%0,%1,%2,%3}, {%4,%5,%6,%7}, {%8,%9}, {%0,%1,%2,%3};"
                 : "+f"(c[0]), "+f"(c[1]), "+f"(c[2]), "+f"(c[3])
                 : "r"(a0), "r"(a1), "r"(a2), "r"(a3), "r"(b0), "r"(b1));
}

extern __shared__ float smem[];

__global__ __launch_bounds__(256) void conv_kernel(const float* __restrict__ x,
                                                   float* __restrict__ out) {
    const int tid  = threadIdx.x;
    const int wid  = tid >> 5;         // warp = one output h row (0..7)
    const int lane = tid & 31;
    const int g    = lane >> 2;        // fragment groupID
    const int tig  = lane & 3;         // fragment threadID-in-group

    const int htile = blockIdx.x;      // 8 h rows each
    const int d     = blockIdx.y;
    const int b     = blockIdx.z;

    const float* __restrict__ xb = x + (size_t)b * CIN * DD * HH_ * WW;
    const uint32_t smem_u = (uint32_t)__cvta_generic_to_shared(smem);

    // ---- init permanent zero slots (ww3 = 64..67 of every row) ----
    for (int i = tid; i < CIN * 10 * 4; i += 256) {
        int c = i / 40;
        int r = (i / 4) % 10;
        int z = i & 3;
        smem[OFF_XT + c * XT_PITCH + r * ROW_PITCH + 64 + z] = 0.f;
    }

    // ---- xT staging: 32c x 10 rows x 16 four-float chunks = 5120 cp16 ----
    const int sc = tid >> 3;           // c 0..31
    const int s8 = tid & 7;
    auto stage_x = [&](int dz) {
        int gd = d + dz - 1;
        bool dok = (gd >= 0) && (gd < DD);
        const float* base = xb + ((size_t)sc * DD + (dok ? gd : 0)) * HH_ * WW;
        #pragma unroll
        for (int j = 0; j < 20; j++) {
            int slot = s8 + 8 * j;     // 0..159
            int hh2  = slot >> 4;      // row 0..9
            int q    = slot & 15;      // 4-float chunk 0..15
            int gh = htile * 8 + hh2 - 1;
            bool ok = dok && (gh >= 0) && (gh < HH_);
            uint32_t dst = smem_u +
                (OFF_XT + sc * XT_PITCH + hh2 * ROW_PITCH + q * 4) * 4;
            cp16_zfill(dst, base + (ok ? gh : 0) * WW + q * 4, ok ? 16 : 0);
        }
    };

    // ---- prologue: stage W (once) + xT(dz=0) ----
    {
        #pragma unroll
        for (int k = 0; k < 31; k++) {
            int idx = tid + 256 * k;           // float4 index, total 7776
            if (idx < W_FLOATS / 4)
                cp16(smem_u + (OFF_W + idx * 4) * 4, g_wt + idx * 4);
        }
        stage_x(0);
        cp_commit();
    }

    // ---- accumulators: C[mi][ni][4] ----
    float acc[4][4][4];
    #pragma unroll
    for (int mi = 0; mi < 4; mi++)
        #pragma unroll
        for (int ni = 0; ni < 4; ni++)
            #pragma unroll
            for (int r = 0; r < 4; r++) acc[mi][ni][r] = 0.f;

    const uint32_t* xtu = reinterpret_cast<const uint32_t*>(smem + OFF_XT);
    const uint32_t* wtu = reinterpret_cast<const uint32_t*>(smem + OFF_W);

    #pragma unroll 1
    for (int dz = 0; dz < 3; dz++) {
        cp_wait0();
        __syncthreads();

        #pragma unroll 1
        for (int t2 = 0; t2 < 9; t2++) {
            const int kh = t2 / 3;
            const int kwm1 = t2 % 3 - 1;
            const int hh2 = wid + kh;                       // 0..9
            const uint32_t* xrow = xtu + hh2 * ROW_PITCH;   // + c*XT_PITCH + ww3
            const uint32_t* wtap = wtu + (dz * 9 + t2) * W_TAP;
            #pragma unroll
            for (int kc = 0; kc < 4; kc++) {
                const int c0 = kc * 8 + tig;
                // B fragments (k = c0 / c0+4, n = ni*8 + g)
                uint32_t b0[4], b1[4];
                #pragma unroll
                for (int ni = 0; ni < 4; ni++) {
                    const uint32_t* wb = wtap + (ni * 8 + g) * WPC + c0;
                    b0[ni] = wb[0];
                    b1[ni] = wb[4];
                }
                // A fragments + MMAs per m-tile
                #pragma unroll
                for (int mi = 0; mi < 4; mi++) {
                    int win = mi * 16 + g + kwm1;           // w' for row m
                    int r0 = (win < 0) ? 65 : win;          // halo -> zero slot
                    int r1 = win + 8;                       // max 64 -> zero slot
                    const uint32_t* xc = xrow + c0 * XT_PITCH;
                    uint32_t a0 = xc[r0];
                    uint32_t a1 = xc[r1];
                    uint32_t a2 = xc[r0 + 4 * XT_PITCH];
                    uint32_t a3 = xc[r1 + 4 * XT_PITCH];
                    #pragma unroll
                    for (int ni = 0; ni < 4; ni++)
                        mma_tf32(acc[mi][ni], a0, a1, a2, a3, b0[ni], b1[ni]);
                }
            }
        }

        if (dz < 2) {
            __syncthreads();           // all reads of xT done before overwrite
            stage_x(dz + 1);
            cp_commit();
        }
    }

    // ---- epilogue: out[b][o][d][h][w] = s*(acc + bias[o]) ----
    const float sb = g_s[b];
    const int h = htile * 8 + wid;
    #pragma unroll
    for (int ni = 0; ni < 4; ni++) {
        const int o0 = ni * 8 + 2 * tig;
        const float bs0 = g_bias[o0];
        const float bs1 = g_bias[o0 + 1];
        float* p0 = out + (((size_t)(b * COUT + o0) * DD + d) * HH_ + h) * WW;
        float* p1 = out + (((size_t)(b * COUT + o0 + 1) * DD + d) * HH_ + h) * WW;
        #pragma unroll
        for (int mi = 0; mi < 4; mi++) {
            const int w = mi * 16 + g;
            p0[w]     = sb * (acc[mi][ni][0] + bs0);
            p1[w]     = sb * (acc[mi][ni][1] + bs1);
            p0[w + 8] = sb * (acc[mi][ni][2] + bs0);
            p1[w + 8] = sb * (acc[mi][ni][3] + bs1);
        }
    }
}

extern "C" void kernel_launch(void* const* d_in, const int* in_sizes, int n_in,
                              void* d_out, int out_size) {
    // x: 16777216, rw: 64, weight: 221184, bias: 256
    const float *x = nullptr, *rw = nullptr, *wt = nullptr, *bi = nullptr;
    for (int i = 0; i < n_in; i++) {
        if (in_sizes[i] == 16777216)     x  = (const float*)d_in[i];
        else if (in_sizes[i] == 221184)  wt = (const float*)d_in[i];
        else if (in_sizes[i] == 256)     bi = (const float*)d_in[i];
        else if (in_sizes[i] == 64)      rw = (const float*)d_in[i];
    }
    float* out = (float*)d_out;

    cudaFuncSetAttribute(conv_kernel,
                         cudaFuncAttributeMaxDynamicSharedMemorySize,
                         SMEM_FLOATS * 4);

    prep_kernel<<<(W_FLOATS + 255) / 256, 256>>>(wt, bi, rw);

    dim3 grid(HH_ / 8, DD, B_);   // (8, 16, 8) = 1024 blocks
    conv_kernel<<<grid, 256, SMEM_FLOATS * 4>>>(x, out);
}